// round 1
// baseline (speedup 1.0000x reference)
#include <cuda_runtime.h>

#define NS 100000
#define ND 100000
#define NE 1600000
#define DIN 256
#define NH 4
#define DH 32
#define HD 128          // NH * DH
#define NEG_SLOPE 0.2f

// ---------------- scratch (device globals; no allocs allowed) ----------------
__device__ __align__(16) float    g_fs[(size_t)NS * HD];    // 51.2 MB projected src feats
__device__ __align__(16) float    g_esrc[NS * NH];
__device__ __align__(16) float    g_edst[ND * NH];
__device__ __align__(16) unsigned g_menc[ND * NH];          // encoded segment max
__device__ __align__(16) float    g_denom[ND * NH];
__device__ __align__(16) float    g_e[(size_t)NE * NH];     // edge logits -> exp values
__device__ __align__(16) float    g_vdst[DIN * NH];         // folded w_dst @ attn_dst

// monotone float->uint encoding for atomicMax on floats (handles negatives)
__device__ __forceinline__ unsigned enc_f(float f) {
    unsigned u = __float_as_uint(f);
    return (u & 0x80000000u) ? ~u : (u | 0x80000000u);
}
__device__ __forceinline__ float dec_f(unsigned u) {
    return (u & 0x80000000u) ? __uint_as_float(u ^ 0x80000000u)
                             : __uint_as_float(~u);
}

// ---------------- K0: init scratch ----------------
__global__ void init_kernel() {
    int i = blockIdx.x * blockDim.x + threadIdx.x;
    if (i < ND * NH) { g_menc[i] = 0u; g_denom[i] = 0.0f; }
}

// ---------------- K1: fs = feat_src @ w_src  (128x128 tile, 8x8 per thread) --
#define BM 128
#define BN 128
#define BK 16
__global__ __launch_bounds__(256) void gemm_fs_kernel(
    const float* __restrict__ A,   // [NS, 256]
    const float* __restrict__ B)   // [256, 128]
{
    __shared__ float As[BK][BM];   // transposed A tile
    __shared__ float Bs[BK][BN];
    const int tid = threadIdx.x;
    const int tr = tid >> 4;       // 0..15
    const int tc = tid & 15;       // 0..15
    const int row0 = blockIdx.x * BM;

    float acc[8][8];
#pragma unroll
    for (int i = 0; i < 8; i++)
#pragma unroll
        for (int j = 0; j < 8; j++) acc[i][j] = 0.0f;

    for (int k0 = 0; k0 < DIN; k0 += BK) {
        // load A tile: 128 rows x 16 cols = 512 float4, 2 per thread
#pragma unroll
        for (int t = 0; t < 2; t++) {
            int f = tid * 2 + t;
            int r = f >> 2, c4 = f & 3;
            int gr = row0 + r;
            float4 v = make_float4(0.f, 0.f, 0.f, 0.f);
            if (gr < NS) v = *(const float4*)(A + (size_t)gr * DIN + k0 + c4 * 4);
            As[c4 * 4 + 0][r] = v.x;
            As[c4 * 4 + 1][r] = v.y;
            As[c4 * 4 + 2][r] = v.z;
            As[c4 * 4 + 3][r] = v.w;
        }
        // load B tile: 16 rows x 128 cols = 512 float4, 2 per thread
#pragma unroll
        for (int t = 0; t < 2; t++) {
            int f = tid * 2 + t;
            int r = f >> 5, c4 = f & 31;
            float4 v = *(const float4*)(B + (size_t)(k0 + r) * BN + c4 * 4);
            *(float4*)&Bs[r][c4 * 4] = v;
        }
        __syncthreads();
#pragma unroll
        for (int k = 0; k < BK; k++) {
            float4 a0 = *(float4*)&As[k][tr * 4];
            float4 a1 = *(float4*)&As[k][64 + tr * 4];
            float4 b0 = *(float4*)&Bs[k][tc * 4];
            float4 b1 = *(float4*)&Bs[k][64 + tc * 4];
            float a[8] = {a0.x, a0.y, a0.z, a0.w, a1.x, a1.y, a1.z, a1.w};
            float b[8] = {b0.x, b0.y, b0.z, b0.w, b1.x, b1.y, b1.z, b1.w};
#pragma unroll
            for (int i = 0; i < 8; i++)
#pragma unroll
                for (int j = 0; j < 8; j++) acc[i][j] += a[i] * b[j];
        }
        __syncthreads();
    }
    // writeback: rows {tr*4+i, 64+tr*4+i}, cols {tc*4+j, 64+tc*4+j}
#pragma unroll
    for (int i = 0; i < 8; i++) {
        int gr = row0 + ((i < 4) ? (tr * 4 + i) : (64 + tr * 4 + (i - 4)));
        if (gr >= NS) continue;
        float4 v0 = make_float4(acc[i][0], acc[i][1], acc[i][2], acc[i][3]);
        float4 v1 = make_float4(acc[i][4], acc[i][5], acc[i][6], acc[i][7]);
        *(float4*)(g_fs + (size_t)gr * HD + tc * 4)      = v0;
        *(float4*)(g_fs + (size_t)gr * HD + 64 + tc * 4) = v1;
    }
}

// ---------------- K2a: fold v_dst[k][h] = sum_j w_dst[k, h*32+j] * attn[h, j]
__global__ void vdst_kernel(const float* __restrict__ wd,
                            const float* __restrict__ attn)
{
    int t = blockIdx.x * blockDim.x + threadIdx.x;
    if (t >= DIN * NH) return;
    int k = t >> 2, h = t & 3;
    float s = 0.0f;
#pragma unroll
    for (int j = 0; j < DH; j++)
        s += wd[(size_t)k * HD + h * DH + j] * attn[h * (2 * DH) + j];
    g_vdst[k * NH + h] = s;
}

// ---------------- K2b: e_dst = feat_dst @ v_dst   (warp per node) -----------
__global__ __launch_bounds__(256) void edst_kernel(const float* __restrict__ fd)
{
    __shared__ float vs[DIN * NH];
    int tid = threadIdx.x;
    for (int i = tid; i < DIN * NH; i += 256) vs[i] = g_vdst[i];
    __syncthreads();
    int warp = tid >> 5, lane = tid & 31;
    int n = blockIdx.x * 8 + warp;
    if (n >= ND) return;
    const float* fr = fd + (size_t)n * DIN;
    float a0 = 0, a1 = 0, a2 = 0, a3 = 0;
#pragma unroll
    for (int t = 0; t < 8; t++) {
        int k = lane + 32 * t;
        float f = fr[k];
        a0 += f * vs[k * NH + 0];
        a1 += f * vs[k * NH + 1];
        a2 += f * vs[k * NH + 2];
        a3 += f * vs[k * NH + 3];
    }
#pragma unroll
    for (int o = 16; o >= 1; o >>= 1) {
        a0 += __shfl_down_sync(0xffffffffu, a0, o);
        a1 += __shfl_down_sync(0xffffffffu, a1, o);
        a2 += __shfl_down_sync(0xffffffffu, a2, o);
        a3 += __shfl_down_sync(0xffffffffu, a3, o);
    }
    if (lane == 0) {
        g_edst[n * NH + 0] = a0;
        g_edst[n * NH + 1] = a1;
        g_edst[n * NH + 2] = a2;
        g_edst[n * NH + 3] = a3;
    }
}

// ---------------- K2c: e_src from fs (warp per node) ------------------------
__global__ __launch_bounds__(256) void esrc_kernel(const float* __restrict__ attn)
{
    int tid = threadIdx.x;
    int warp = tid >> 5, lane = tid & 31;
    int n = blockIdx.x * 8 + warp;
    if (n >= NS) return;
    int h = lane >> 3;
    int j = (lane & 7) * 4;
    float4 f = *(const float4*)&g_fs[(size_t)n * HD + lane * 4];
    const float* ar = attn + h * (2 * DH) + DH + j;   // second half of attn row
    float p = f.x * ar[0] + f.y * ar[1] + f.z * ar[2] + f.w * ar[3];
    p += __shfl_down_sync(0xffffffffu, p, 4, 8);
    p += __shfl_down_sync(0xffffffffu, p, 2, 8);
    p += __shfl_down_sync(0xffffffffu, p, 1, 8);
    if ((lane & 7) == 0) g_esrc[n * NH + h] = p;
}

// ---------------- K3: edge logits + leaky relu + segment max ----------------
__global__ void edge_logits_kernel(const int* __restrict__ src,
                                   const int* __restrict__ dst)
{
    int i = blockIdx.x * blockDim.x + threadIdx.x;
    if (i >= NE) return;
    int s = src[i], d = dst[i];
    float4 es = *(const float4*)&g_esrc[(size_t)s * NH];
    float4 ed = *(const float4*)&g_edst[(size_t)d * NH];
    float4 e;
    e.x = es.x + ed.x; e.x = e.x > 0.f ? e.x : NEG_SLOPE * e.x;
    e.y = es.y + ed.y; e.y = e.y > 0.f ? e.y : NEG_SLOPE * e.y;
    e.z = es.z + ed.z; e.z = e.z > 0.f ? e.z : NEG_SLOPE * e.z;
    e.w = es.w + ed.w; e.w = e.w > 0.f ? e.w : NEG_SLOPE * e.w;
    *(float4*)&g_e[(size_t)i * NH] = e;
    atomicMax(&g_menc[d * NH + 0], enc_f(e.x));
    atomicMax(&g_menc[d * NH + 1], enc_f(e.y));
    atomicMax(&g_menc[d * NH + 2], enc_f(e.z));
    atomicMax(&g_menc[d * NH + 3], enc_f(e.w));
}

// ---------------- K4: exp(e - m) + segment sum ------------------------------
__global__ void edge_exp_kernel(const int* __restrict__ dst)
{
    int i = blockIdx.x * blockDim.x + threadIdx.x;
    if (i >= NE) return;
    int d = dst[i];
    float4 e = *(const float4*)&g_e[(size_t)i * NH];
    float m0 = dec_f(g_menc[d * NH + 0]);
    float m1 = dec_f(g_menc[d * NH + 1]);
    float m2 = dec_f(g_menc[d * NH + 2]);
    float m3 = dec_f(g_menc[d * NH + 3]);
    float4 ex;
    ex.x = expf(e.x - m0);
    ex.y = expf(e.y - m1);
    ex.z = expf(e.z - m2);
    ex.w = expf(e.w - m3);
    *(float4*)&g_e[(size_t)i * NH] = ex;
    atomicAdd(&g_denom[d * NH + 0], ex.x);
    atomicAdd(&g_denom[d * NH + 1], ex.y);
    atomicAdd(&g_denom[d * NH + 2], ex.z);
    atomicAdd(&g_denom[d * NH + 3], ex.w);
}

// ---------------- K5: aggregate msg = fs[src]*a into out[dst] (warp/edge) ---
__global__ __launch_bounds__(256) void aggregate_kernel(
    const int* __restrict__ src, const int* __restrict__ dst,
    float* __restrict__ out)
{
    int gt = blockIdx.x * blockDim.x + threadIdx.x;
    int e = gt >> 5;
    int lane = threadIdx.x & 31;
    if (e >= NE) return;
    int s = src[e], d = dst[e];
    int h = lane >> 3;
    float ex  = g_e[(size_t)e * NH + h];
    float den = g_denom[(size_t)d * NH + h];
    float a = ex / den;
    float4 f = *(const float4*)&g_fs[(size_t)s * HD + lane * 4];
    float* op = out + (size_t)d * HD + lane * 4;
    asm volatile("red.global.add.v4.f32 [%0], {%1,%2,%3,%4};"
                 :: "l"(op), "f"(f.x * a), "f"(f.y * a), "f"(f.z * a), "f"(f.w * a)
                 : "memory");
}

// ---------------- K6: relu in place -----------------------------------------
__global__ void relu_kernel(float* __restrict__ out, int n4)
{
    int i = blockIdx.x * blockDim.x + threadIdx.x;
    if (i >= n4) return;
    float4 v = *(float4*)(out + (size_t)i * 4);
    v.x = fmaxf(v.x, 0.f); v.y = fmaxf(v.y, 0.f);
    v.z = fmaxf(v.z, 0.f); v.w = fmaxf(v.w, 0.f);
    *(float4*)(out + (size_t)i * 4) = v;
}

// ---------------- launch -----------------------------------------------------
extern "C" void kernel_launch(void* const* d_in, const int* in_sizes, int n_in,
                              void* d_out, int out_size)
{
    const float* feat_src = (const float*)d_in[0];
    const float* feat_dst = (const float*)d_in[1];
    const float* w_src    = (const float*)d_in[2];
    const float* w_dst    = (const float*)d_in[3];
    const float* attn     = (const float*)d_in[4];
    const int*   src_idx  = (const int*)d_in[5];
    const int*   dst_idx  = (const int*)d_in[6];
    float* out = (float*)d_out;

    cudaMemsetAsync(d_out, 0, (size_t)out_size * sizeof(float), 0);
    init_kernel<<<(ND * NH + 255) / 256, 256>>>();
    gemm_fs_kernel<<<(NS + BM - 1) / BM, 256>>>(feat_src, w_src);
    vdst_kernel<<<(DIN * NH + 255) / 256, 256>>>(w_dst, attn);
    edst_kernel<<<(ND + 7) / 8, 256>>>(feat_dst);
    esrc_kernel<<<(NS + 7) / 8, 256>>>(attn);
    edge_logits_kernel<<<NE / 256, 256>>>(src_idx, dst_idx);
    edge_exp_kernel<<<NE / 256, 256>>>(dst_idx);
    aggregate_kernel<<<(size_t)NE * 32 / 256, 256>>>(src_idx, dst_idx, out);
    relu_kernel<<<(out_size / 4 + 255) / 256, 256>>>(out, out_size / 4);
}

// round 4
// speedup vs baseline: 1.5163x; 1.5163x over previous
#include <cuda_runtime.h>
#include <math_constants.h>

#define NS 100000
#define ND 100000
#define NE 1600000
#define DIN 256
#define NH 4
#define DH 32
#define HD 128          // NH * DH
#define NEG_SLOPE 0.2f
#define NBLK ((ND + 255) / 256)   // 391 scan blocks

// ---------------- scratch (device globals; no allocs allowed) ----------------
__device__ __align__(16) float g_fs[(size_t)NS * HD];    // 51.2 MB projected src feats
__device__ __align__(16) float g_esrc[NS * NH];
__device__ __align__(16) float g_edst[ND * NH];
__device__ __align__(16) float g_e[(size_t)NE * NH];     // edge logits (post leaky-relu)
__device__ __align__(16) float g_vdst[DIN * NH];         // folded w_dst @ attn_dst
__device__ int  g_cnt[ND];        // per-dst degree
__device__ int  g_wpos[ND];       // scatter cursors
__device__ int  g_base[ND];       // block-local exclusive scan
__device__ int  g_bsum[NBLK];     // per-block totals
__device__ int  g_boff[NBLK];     // scanned block offsets
__device__ __align__(8) int2 g_sorted[NE];   // {edge_id, src} sorted by dst

// ---------------- K0: init counters ----------------
__global__ void init_kernel() {
    int i = blockIdx.x * blockDim.x + threadIdx.x;
    if (i < ND) { g_cnt[i] = 0; g_wpos[i] = 0; }
}

// ---------------- K1: fs = feat_src @ w_src  (128x128 tile, 8x8/thread) -----
#define BM 128
#define BN 128
#define BK 16
__global__ __launch_bounds__(256) void gemm_fs_kernel(
    const float* __restrict__ A,   // [NS, 256]
    const float* __restrict__ B)   // [256, 128]
{
    __shared__ float As[BK][BM];
    __shared__ float Bs[BK][BN];
    const int tid = threadIdx.x;
    const int tr = tid >> 4;
    const int tc = tid & 15;
    const int row0 = blockIdx.x * BM;

    float acc[8][8];
#pragma unroll
    for (int i = 0; i < 8; i++)
#pragma unroll
        for (int j = 0; j < 8; j++) acc[i][j] = 0.0f;

    for (int k0 = 0; k0 < DIN; k0 += BK) {
#pragma unroll
        for (int t = 0; t < 2; t++) {
            int f = tid * 2 + t;
            int r = f >> 2, c4 = f & 3;
            int gr = row0 + r;
            float4 v = make_float4(0.f, 0.f, 0.f, 0.f);
            if (gr < NS) v = *(const float4*)(A + (size_t)gr * DIN + k0 + c4 * 4);
            As[c4 * 4 + 0][r] = v.x;
            As[c4 * 4 + 1][r] = v.y;
            As[c4 * 4 + 2][r] = v.z;
            As[c4 * 4 + 3][r] = v.w;
        }
#pragma unroll
        for (int t = 0; t < 2; t++) {
            int f = tid * 2 + t;
            int r = f >> 5, c4 = f & 31;
            float4 v = *(const float4*)(B + (size_t)(k0 + r) * BN + c4 * 4);
            *(float4*)&Bs[r][c4 * 4] = v;
        }
        __syncthreads();
#pragma unroll
        for (int k = 0; k < BK; k++) {
            float4 a0 = *(float4*)&As[k][tr * 4];
            float4 a1 = *(float4*)&As[k][64 + tr * 4];
            float4 b0 = *(float4*)&Bs[k][tc * 4];
            float4 b1 = *(float4*)&Bs[k][64 + tc * 4];
            float a[8] = {a0.x, a0.y, a0.z, a0.w, a1.x, a1.y, a1.z, a1.w};
            float b[8] = {b0.x, b0.y, b0.z, b0.w, b1.x, b1.y, b1.z, b1.w};
#pragma unroll
            for (int i = 0; i < 8; i++)
#pragma unroll
                for (int j = 0; j < 8; j++) acc[i][j] += a[i] * b[j];
        }
        __syncthreads();
    }
#pragma unroll
    for (int i = 0; i < 8; i++) {
        int gr = row0 + ((i < 4) ? (tr * 4 + i) : (64 + tr * 4 + (i - 4)));
        if (gr >= NS) continue;
        float4 v0 = make_float4(acc[i][0], acc[i][1], acc[i][2], acc[i][3]);
        float4 v1 = make_float4(acc[i][4], acc[i][5], acc[i][6], acc[i][7]);
        *(float4*)(g_fs + (size_t)gr * HD + tc * 4)      = v0;
        *(float4*)(g_fs + (size_t)gr * HD + 64 + tc * 4) = v1;
    }
}

// ---------------- K2a: fold v_dst[k][h] = sum_j w_dst[k,h*32+j]*attn[h,j] ---
__global__ void vdst_kernel(const float* __restrict__ wd,
                            const float* __restrict__ attn)
{
    int t = blockIdx.x * blockDim.x + threadIdx.x;
    if (t >= DIN * NH) return;
    int k = t >> 2, h = t & 3;
    float s = 0.0f;
#pragma unroll
    for (int j = 0; j < DH; j++)
        s += wd[(size_t)k * HD + h * DH + j] * attn[h * (2 * DH) + j];
    g_vdst[k * NH + h] = s;
}

// ---------------- K2b: e_dst = feat_dst @ v_dst  (warp/node, float4 LDS) ----
__global__ __launch_bounds__(256) void edst_kernel(const float* __restrict__ fd)
{
    __shared__ float4 vs4[DIN];
    int tid = threadIdx.x;
    for (int i = tid; i < DIN; i += 256) vs4[i] = *(const float4*)&g_vdst[i * NH];
    __syncthreads();
    int warp = tid >> 5, lane = tid & 31;
    int n = blockIdx.x * 8 + warp;
    if (n >= ND) return;
    const float* fr = fd + (size_t)n * DIN;
    float a0 = 0, a1 = 0, a2 = 0, a3 = 0;
#pragma unroll
    for (int t = 0; t < 8; t++) {
        int k = lane + 32 * t;
        float f = fr[k];
        float4 v = vs4[k];
        a0 += f * v.x; a1 += f * v.y; a2 += f * v.z; a3 += f * v.w;
    }
#pragma unroll
    for (int o = 16; o >= 1; o >>= 1) {
        a0 += __shfl_down_sync(0xffffffffu, a0, o);
        a1 += __shfl_down_sync(0xffffffffu, a1, o);
        a2 += __shfl_down_sync(0xffffffffu, a2, o);
        a3 += __shfl_down_sync(0xffffffffu, a3, o);
    }
    if (lane == 0) {
        g_edst[n * NH + 0] = a0;
        g_edst[n * NH + 1] = a1;
        g_edst[n * NH + 2] = a2;
        g_edst[n * NH + 3] = a3;
    }
}

// ---------------- K2c: e_src from fs (warp per node) ------------------------
__global__ __launch_bounds__(256) void esrc_kernel(const float* __restrict__ attn)
{
    int tid = threadIdx.x;
    int warp = tid >> 5, lane = tid & 31;
    int n = blockIdx.x * 8 + warp;
    if (n >= NS) return;
    int h = lane >> 3;
    int j = (lane & 7) * 4;
    float4 f = *(const float4*)&g_fs[(size_t)n * HD + lane * 4];
    const float* ar = attn + h * (2 * DH) + DH + j;
    float p = f.x * ar[0] + f.y * ar[1] + f.z * ar[2] + f.w * ar[3];
    p += __shfl_down_sync(0xffffffffu, p, 4, 8);
    p += __shfl_down_sync(0xffffffffu, p, 2, 8);
    p += __shfl_down_sync(0xffffffffu, p, 1, 8);
    if ((lane & 7) == 0) g_esrc[n * NH + h] = p;
}

// ---------------- K3: edge logits + leaky relu + dst histogram --------------
__global__ void edge_logits_kernel(const int* __restrict__ src,
                                   const int* __restrict__ dst)
{
    int i = blockIdx.x * blockDim.x + threadIdx.x;
    if (i >= NE) return;
    int s = src[i], d = dst[i];
    float4 es = *(const float4*)&g_esrc[(size_t)s * NH];
    float4 ed = *(const float4*)&g_edst[(size_t)d * NH];
    float4 e;
    e.x = es.x + ed.x; e.x = e.x > 0.f ? e.x : NEG_SLOPE * e.x;
    e.y = es.y + ed.y; e.y = e.y > 0.f ? e.y : NEG_SLOPE * e.y;
    e.z = es.z + ed.z; e.z = e.z > 0.f ? e.z : NEG_SLOPE * e.z;
    e.w = es.w + ed.w; e.w = e.w > 0.f ? e.w : NEG_SLOPE * e.w;
    *(float4*)&g_e[(size_t)i * NH] = e;
    atomicAdd(&g_cnt[d], 1);
}

// ---------------- K4a: per-block exclusive scan of g_cnt --------------------
__global__ __launch_bounds__(256) void scan_block_kernel()
{
    int t = threadIdx.x;
    int i = blockIdx.x * 256 + t;
    int c = (i < ND) ? g_cnt[i] : 0;
    int lane = t & 31, w = t >> 5;
    int inc = c;
#pragma unroll
    for (int o = 1; o < 32; o <<= 1) {
        int n = __shfl_up_sync(0xffffffffu, inc, o);
        if (lane >= o) inc += n;
    }
    __shared__ int ws[8];
    if (lane == 31) ws[w] = inc;
    __syncthreads();
    if (t < 8) {
        int v = ws[t];
        int inc2 = v;
#pragma unroll
        for (int o = 1; o < 8; o <<= 1) {
            int n = __shfl_up_sync(0x000000ffu, inc2, o);
            if (t >= o) inc2 += n;
        }
        ws[t] = inc2 - v;   // exclusive warp offset
    }
    __syncthreads();
    int excl = inc - c + ws[w];
    if (i < ND) g_base[i] = excl;
    if (t == 255) g_bsum[blockIdx.x] = excl + c;
}

// ---------------- K4b: scan the 391 block sums ------------------------------
__global__ __launch_bounds__(512) void scan_top_kernel()
{
    int t = threadIdx.x;
    int c = (t < NBLK) ? g_bsum[t] : 0;
    int lane = t & 31, w = t >> 5;
    int inc = c;
#pragma unroll
    for (int o = 1; o < 32; o <<= 1) {
        int n = __shfl_up_sync(0xffffffffu, inc, o);
        if (lane >= o) inc += n;
    }
    __shared__ int ws[16];
    if (lane == 31) ws[w] = inc;
    __syncthreads();
    if (t < 16) {
        int v = ws[t];
        int inc2 = v;
#pragma unroll
        for (int o = 1; o < 16; o <<= 1) {
            int n = __shfl_up_sync(0x0000ffffu, inc2, o);
            if (t >= o) inc2 += n;
        }
        ws[t] = inc2 - v;
    }
    __syncthreads();
    if (t < NBLK) g_boff[t] = inc - c + ws[w];
}

// ---------------- K5: scatter edges into dst-sorted order -------------------
__global__ void scatter_kernel(const int* __restrict__ src,
                               const int* __restrict__ dst)
{
    int i = blockIdx.x * blockDim.x + threadIdx.x;
    if (i >= NE) return;
    int d = dst[i];
    int s = src[i];                          // issue both loads before the atomic
    int pos = atomicAdd(&g_wpos[d], 1);
    int slot = g_base[d] + g_boff[d >> 8] + pos;
    g_sorted[slot] = make_int2(i, s);
}

// ---------------- K6: warp-per-dst online-softmax aggregation ---------------
__global__ __launch_bounds__(256) void aggregate_kernel(float* __restrict__ out)
{
    int warp = threadIdx.x >> 5, lane = threadIdx.x & 31;
    int d = blockIdx.x * 8 + warp;
    if (d >= ND) return;
    int base = g_base[d] + g_boff[d >> 8];
    int cnt  = g_cnt[d];
    int h = lane >> 3;

    float m = -CUDART_INF_F;
    float denom = 0.0f;
    float4 acc = make_float4(0.f, 0.f, 0.f, 0.f);

    int2 es; float e; float4 f;
    if (cnt > 0) {
        es = g_sorted[base];
        e  = __ldg(&g_e[(size_t)es.x * NH + h]);
        f  = *(const float4*)&g_fs[(size_t)es.y * HD + lane * 4];
    }
    for (int j = 0; j < cnt; j++) {
        int2 es_n; float e_n; float4 f_n;
        if (j + 1 < cnt) {                       // prefetch next edge
            es_n = g_sorted[base + j + 1];
            e_n  = __ldg(&g_e[(size_t)es_n.x * NH + h]);
            f_n  = *(const float4*)&g_fs[(size_t)es_n.y * HD + lane * 4];
        }
        if (e > m) {
            float sc = __expf(m - e);            // exp(-inf)=0 on first edge
            m = e;
            denom = denom * sc + 1.0f;
            acc.x = acc.x * sc + f.x;
            acc.y = acc.y * sc + f.y;
            acc.z = acc.z * sc + f.z;
            acc.w = acc.w * sc + f.w;
        } else {
            float w = __expf(e - m);
            denom += w;
            acc.x += w * f.x;
            acc.y += w * f.y;
            acc.z += w * f.z;
            acc.w += w * f.w;
        }
        es = es_n; e = e_n; f = f_n;
    }
    float inv = (cnt > 0) ? 1.0f / denom : 0.0f;
    float4 o;
    o.x = fmaxf(acc.x * inv, 0.f);
    o.y = fmaxf(acc.y * inv, 0.f);
    o.z = fmaxf(acc.z * inv, 0.f);
    o.w = fmaxf(acc.w * inv, 0.f);
    *(float4*)(out + (size_t)d * HD + lane * 4) = o;
}

// ---------------- launch -----------------------------------------------------
extern "C" void kernel_launch(void* const* d_in, const int* in_sizes, int n_in,
                              void* d_out, int out_size)
{
    const float* feat_src = (const float*)d_in[0];
    const float* feat_dst = (const float*)d_in[1];
    const float* w_src    = (const float*)d_in[2];
    const float* w_dst    = (const float*)d_in[3];
    const float* attn     = (const float*)d_in[4];
    const int*   src_idx  = (const int*)d_in[5];
    const int*   dst_idx  = (const int*)d_in[6];
    float* out = (float*)d_out;

    init_kernel<<<(ND + 255) / 256, 256>>>();
    gemm_fs_kernel<<<(NS + BM - 1) / BM, 256>>>(feat_src, w_src);
    vdst_kernel<<<(DIN * NH + 255) / 256, 256>>>(w_dst, attn);
    edst_kernel<<<(ND + 7) / 8, 256>>>(feat_dst);
    esrc_kernel<<<(NS + 7) / 8, 256>>>(attn);
    edge_logits_kernel<<<NE / 256, 256>>>(src_idx, dst_idx);
    scan_block_kernel<<<NBLK, 256>>>();
    scan_top_kernel<<<1, 512>>>();
    scatter_kernel<<<NE / 256, 256>>>(src_idx, dst_idx);
    aggregate_kernel<<<(ND + 7) / 8, 256>>>(out);
}